// round 3
// baseline (speedup 1.0000x reference)
#include <cuda_runtime.h>
#include <math.h>

#define DEV_INLINE __device__ __forceinline__

constexpr int DD  = 256;
constexpr int MC  = 50;
constexpr int NP  = 65536;
constexpr int NT  = NP + MC;      // 65586
constexpr int LDQ = 3 * DD;       // 768
constexpr float SCALE = 0.0625f;  // D^-0.5

// ------------------------- scratch (device globals; no runtime alloc) -----
__device__ float g_qkv[(size_t)NT * LDQ];
__device__ float g_L  [(size_t)NP * MC];
__device__ float g_rm [MC];
__device__ float g_rz [MC];
__device__ float g_occ[MC * DD];
__device__ float g_osc[MC * DD];
__device__ float g_ocp[(size_t)NP * DD];
__device__ float g_ql [(size_t)NP * DD];
__device__ float g_kl [(size_t)NP * DD];
__device__ float g_ks [DD];
__device__ float g_kv [DD * DD];
__device__ float g_fm [(size_t)NP * DD];
__device__ float g_t1 [(size_t)NP * DD];
__device__ float g_osp[(size_t)NP * DD];
__device__ float g_ga [(size_t)NP * DD];
__device__ float g_gb [(size_t)NP * DD];
__device__ float g_Acc[MC], g_Asc[MC];
__device__ float g_Acp[NP], g_Asp[NP];
__device__ float g_mZ [8];
__device__ float g_h  [4 * DD];
__device__ float g_f  [4 * DD];
__device__ float g_g1 [2 * DD];

// ------------------------- reduction helpers ------------------------------
DEV_INLINE float warpSum(float v) {
#pragma unroll
    for (int o = 16; o; o >>= 1) v += __shfl_xor_sync(0xffffffffu, v, o);
    return v;
}
DEV_INLINE float warpMax(float v) {
#pragma unroll
    for (int o = 16; o; o >>= 1) v = fmaxf(v, __shfl_xor_sync(0xffffffffu, v, o));
    return v;
}
DEV_INLINE float blockSum256(float v) {
    __shared__ float red[8];
    v = warpSum(v);
    __syncthreads();
    if ((threadIdx.x & 31) == 0) red[threadIdx.x >> 5] = v;
    __syncthreads();
    float t = 0.f;
#pragma unroll
    for (int i = 0; i < 8; i++) t += red[i];
    return t;
}
DEV_INLINE float blockMax256(float v) {
    __shared__ float red[8];
    v = warpMax(v);
    __syncthreads();
    if ((threadIdx.x & 31) == 0) red[threadIdx.x >> 5] = v;
    __syncthreads();
    float t = -1e30f;
#pragma unroll
    for (int i = 0; i < 8; i++) t = fmaxf(t, red[i]);
    return t;
}

__global__ void zerok(float* p, int n) {
    int i = blockIdx.x * 256 + threadIdx.x;
    if (i < n) p[i] = 0.f;
}

// ------------------------- SGEMM: C = A@B (+bias)(+add) -------------------
// A (M,K) row-major, B (K,N) row-major. BM=128 BN=64 BK=16, 256 thr, 8x4/thr.
// Requires K%16==0, N%64==0.
__global__ void __launch_bounds__(256) sgemm(
    const float* __restrict__ A, const float* __restrict__ B,
    float* __restrict__ C, const float* __restrict__ bias,
    const float* __restrict__ add, int M, int K, int N)
{
    __shared__ float As[16][136];
    __shared__ float Bs[16][64];
    int tid = threadIdx.x;
    int bm = blockIdx.y * 128, bn = blockIdx.x * 64;
    int tx = tid & 15, ty = tid >> 4;

    float acc[8][4];
#pragma unroll
    for (int i = 0; i < 8; i++)
#pragma unroll
        for (int j = 0; j < 4; j++) acc[i][j] = 0.f;

    int ar0 = tid >> 2;        // 0..63
    int ac4 = tid & 3;         // float4 col group
    int br  = tid >> 4;        // 0..15
    int bc4 = tid & 15;        // 0..15

    for (int k0 = 0; k0 < K; k0 += 16) {
        int gr0 = bm + ar0, gr1 = bm + ar0 + 64;
        float4 va0 = (gr0 < M) ? __ldg((const float4*)(A + (size_t)gr0 * K + k0 + ac4 * 4))
                               : make_float4(0.f, 0.f, 0.f, 0.f);
        float4 va1 = (gr1 < M) ? __ldg((const float4*)(A + (size_t)gr1 * K + k0 + ac4 * 4))
                               : make_float4(0.f, 0.f, 0.f, 0.f);
        float4 vb  = __ldg((const float4*)(B + (size_t)(k0 + br) * N + bn + bc4 * 4));

        As[ac4 * 4 + 0][ar0] = va0.x;  As[ac4 * 4 + 1][ar0] = va0.y;
        As[ac4 * 4 + 2][ar0] = va0.z;  As[ac4 * 4 + 3][ar0] = va0.w;
        As[ac4 * 4 + 0][ar0 + 64] = va1.x;  As[ac4 * 4 + 1][ar0 + 64] = va1.y;
        As[ac4 * 4 + 2][ar0 + 64] = va1.z;  As[ac4 * 4 + 3][ar0 + 64] = va1.w;
        *(float4*)&Bs[br][bc4 * 4] = vb;
        __syncthreads();

#pragma unroll
        for (int kk = 0; kk < 16; kk++) {
            float a[8], b[4];
#pragma unroll
            for (int i = 0; i < 8; i++) a[i] = As[kk][ty * 8 + i];
#pragma unroll
            for (int j = 0; j < 4; j++) b[j] = Bs[kk][tx * 4 + j];
#pragma unroll
            for (int i = 0; i < 8; i++)
#pragma unroll
                for (int j = 0; j < 4; j++) acc[i][j] += a[i] * b[j];
        }
        __syncthreads();
    }

#pragma unroll
    for (int i = 0; i < 8; i++) {
        int gr = bm + ty * 8 + i;
        if (gr < M) {
#pragma unroll
            for (int j = 0; j < 4; j++) {
                int gc = bn + tx * 4 + j;
                float v = acc[i][j];
                if (bias) v += bias[gc];
                if (add)  v += add[(size_t)gr * N + gc];
                C[(size_t)gr * N + gc] = v;
            }
        }
    }
}

// ------------------------- split-K  C[256,256] += A^T B -------------------
// A (J,256) stride lda, B (J,256) stride ldb. grid (4,4,S).
__global__ void __launch_bounds__(256) atb_gemm(
    const float* __restrict__ A, int lda,
    const float* __restrict__ B, int ldb,
    float* __restrict__ C, int CHUNK)
{
    __shared__ float As[16][68];
    __shared__ float Bs[16][68];
    int tid = threadIdx.x;
    int c0 = blockIdx.x * 64, d0 = blockIdx.y * 64;
    int j0 = blockIdx.z * CHUNK;
    int tx = tid & 15, ty = tid >> 4;
    int lr = tid >> 4, lc4 = tid & 15;

    float acc[4][4];
#pragma unroll
    for (int i = 0; i < 4; i++)
#pragma unroll
        for (int j = 0; j < 4; j++) acc[i][j] = 0.f;

    for (int j = j0; j < j0 + CHUNK; j += 16) {
        *(float4*)&As[lr][lc4 * 4] = __ldg((const float4*)(A + (size_t)(j + lr) * lda + c0 + lc4 * 4));
        *(float4*)&Bs[lr][lc4 * 4] = __ldg((const float4*)(B + (size_t)(j + lr) * ldb + d0 + lc4 * 4));
        __syncthreads();
#pragma unroll
        for (int kk = 0; kk < 16; kk++) {
            float a[4], b[4];
#pragma unroll
            for (int i = 0; i < 4; i++) a[i] = As[kk][ty * 4 + i];
#pragma unroll
            for (int j2 = 0; j2 < 4; j2++) b[j2] = Bs[kk][tx * 4 + j2];
#pragma unroll
            for (int i = 0; i < 4; i++)
#pragma unroll
                for (int j2 = 0; j2 < 4; j2++) acc[i][j2] += a[i] * b[j2];
        }
        __syncthreads();
    }
#pragma unroll
    for (int i = 0; i < 4; i++)
#pragma unroll
        for (int j2 = 0; j2 < 4; j2++)
            atomicAdd(&C[(size_t)(c0 + ty * 4 + i) * DD + d0 + tx * 4 + j2], acc[i][j2]);
}

// ---- fused attention, 50 keys: out = softmax(q*s @ kc^T) @ vc ------------
__global__ void __launch_bounds__(256) attn_small_k(
    const float* __restrict__ qkv, int qrow0, int nrows, float* __restrict__ out)
{
    int warp = threadIdx.x >> 5, lane = threadIdx.x & 31;
    int r = blockIdx.x * 8 + warp;
    if (r >= nrows) return;
    const float* q = qkv + (size_t)(qrow0 + r) * LDQ;
    float qreg[8];
#pragma unroll
    for (int u = 0; u < 8; u++) qreg[u] = q[lane + 32 * u] * SCALE;

    float mrun = -1e30f, zrun = 0.f, acc[8];
#pragma unroll
    for (int u = 0; u < 8; u++) acc[u] = 0.f;

    for (int i = 0; i < MC; i++) {
        const float* kr = qkv + (size_t)i * LDQ + DD;
        float s = 0.f;
#pragma unroll
        for (int u = 0; u < 8; u++) s += qreg[u] * __ldg(&kr[lane + 32 * u]);
#pragma unroll
        for (int o = 16; o; o >>= 1) s += __shfl_xor_sync(0xffffffffu, s, o);
        float nm = fmaxf(mrun, s);
        float corr = __expf(mrun - nm);
        float w = __expf(s - nm);
        zrun = zrun * corr + w;
        const float* vr = qkv + (size_t)i * LDQ + 2 * DD;
#pragma unroll
        for (int u = 0; u < 8; u++) acc[u] = acc[u] * corr + w * __ldg(&vr[lane + 32 * u]);
        mrun = nm;
    }
    float iz = 1.f / zrun;
#pragma unroll
    for (int u = 0; u < 8; u++) out[(size_t)r * DD + lane + 32 * u] = acc[u] * iz;
}

// ---- cross-celltypes logits: L[j][i] = s * qc_i . kp_j -------------------
__global__ void __launch_bounds__(256) cac_logits_k(
    const float* __restrict__ qkv, float* __restrict__ L)
{
    int warp = threadIdx.x >> 5, lane = threadIdx.x & 31;
    int j = blockIdx.x * 8 + warp;
    const float* kp = qkv + (size_t)(MC + j) * LDQ + DD;
    float kreg[8];
#pragma unroll
    for (int u = 0; u < 8; u++) kreg[u] = kp[lane + 32 * u];
    __shared__ float lg[8][52];
    for (int i = 0; i < MC; i++) {
        const float* qr = qkv + (size_t)i * LDQ;
        float s = 0.f;
#pragma unroll
        for (int u = 0; u < 8; u++) s += kreg[u] * __ldg(&qr[lane + 32 * u]);
#pragma unroll
        for (int o = 16; o; o >>= 1) s += __shfl_xor_sync(0xffffffffu, s, o);
        if (lane == 0) lg[warp][i] = s * SCALE;
    }
    __syncwarp();
    for (int i = lane; i < MC; i += 32) L[(size_t)j * MC + i] = lg[warp][i];
}

__global__ void __launch_bounds__(256) cac_rowstats(
    const float* __restrict__ L, float* __restrict__ m, float* __restrict__ z)
{
    int i = blockIdx.x, tid = threadIdx.x;
    float mx = -1e30f;
    for (int j = tid; j < NP; j += 256) mx = fmaxf(mx, L[(size_t)j * MC + i]);
    float mm = blockMax256(mx);
    float s = 0.f;
    for (int j = tid; j < NP; j += 256) s += __expf(L[(size_t)j * MC + i] - mm);
    float ss = blockSum256(s);
    if (tid == 0) { m[i] = mm; z[i] = ss; }
}

// occ[i][d] += sum_j exp(L[j][i]-m[i]) * vp[j][d]
__global__ void __launch_bounds__(256) cac_out_k(
    const float* __restrict__ L, const float* __restrict__ m,
    const float* __restrict__ vp, float* __restrict__ occ)
{
    __shared__ float e[MC];
    int tid = threadIdx.x;
    int c = tid & 127, half = tid >> 7;
    int d0 = blockIdx.y * 128;
    int j0 = blockIdx.x * 512;
    float acc[25];
#pragma unroll
    for (int ii = 0; ii < 25; ii++) acc[ii] = 0.f;
    for (int j = j0; j < j0 + 512; j++) {
        if (tid < MC) e[tid] = __expf(L[(size_t)j * MC + tid] - m[tid]);
        __syncthreads();
        float v = __ldg(&vp[(size_t)j * LDQ + d0 + c]);
#pragma unroll
        for (int ii = 0; ii < 25; ii++) acc[ii] += e[half * 25 + ii] * v;
        __syncthreads();
    }
#pragma unroll
    for (int ii = 0; ii < 25; ii++)
        atomicAdd(&occ[(half * 25 + ii) * DD + d0 + c], acc[ii]);
}

__global__ void occ_scale_k(float* occ, const float* z) {
    occ[blockIdx.x * DD + threadIdx.x] /= z[blockIdx.x];
}

// ---- linear-attention feature map ----------------------------------------
__global__ void __launch_bounds__(256) linearize_k(
    const float* __restrict__ qkv, const float* __restrict__ sl,
    float* __restrict__ out, int off)
{
    int row = blockIdx.x, c = threadIdx.x;
    float x = qkv[(size_t)(MC + row) * LDQ + off + c];
    float sp = log1pf(__expf(sl[c]));
    float l = (fmaxf(x, 0.f) + 1e-6f) / sp;
    float l2 = l * l, l3 = l2 * l;
    float s2 = blockSum256(l2);
    float s6 = blockSum256(l3 * l3);
    out[(size_t)row * DD + c] = l3 * (sqrtf(s2) / sqrtf(s6));
}

__global__ void __launch_bounds__(256) colsum_k(
    const float* __restrict__ kl, float* __restrict__ ks)
{
    int c = threadIdx.x;
    size_t j0 = (size_t)blockIdx.x * 256;
    float s = 0.f;
    for (int j = 0; j < 256; j++) s += kl[(j0 + j) * DD + c];
    atomicAdd(&ks[c], s);
}

// ql <- ql / (ql . ksum + 1e-6)
__global__ void __launch_bounds__(256) zfac_k(
    float* __restrict__ ql, const float* __restrict__ ks)
{
    int row = blockIdx.x, c = threadIdx.x;
    float v = ql[(size_t)row * DD + c];
    float d = blockSum256(v * ks[c]);
    ql[(size_t)row * DD + c] = v / (d + 1e-6f);
}

// ---- 5x5 depthwise conv on vp viewed as 256x256xD ------------------------
__global__ void __launch_bounds__(256) dwconv_k(
    const float* __restrict__ qkv, const float* __restrict__ w,
    const float* __restrict__ b, float* __restrict__ fm)
{
    int p = blockIdx.x, c = threadIdx.x;
    int y = p >> 8, x = p & 255;
    const float* vp = qkv + (size_t)MC * LDQ + 2 * DD;
    float acc = b[c];
#pragma unroll
    for (int dy = 0; dy < 5; dy++) {
        int yy = y + dy - 2;
        if ((unsigned)yy >= 256u) continue;
#pragma unroll
        for (int dx = 0; dx < 5; dx++) {
            int xx = x + dx - 2;
            if ((unsigned)xx >= 256u) continue;
            acc += __ldg(&vp[(size_t)(yy * 256 + xx) * LDQ + c]) * __ldg(&w[c * 25 + dy * 5 + dx]);
        }
    }
    fm[(size_t)p * DD + c] = acc;
}

// ---- gated scalar: A[i] = sum_c tanh(ga)*sigmoid(gb)*Wc[c] + bc ----------
__global__ void __launch_bounds__(256) gated_k(
    const float* __restrict__ ga, const float* __restrict__ gb,
    const float* __restrict__ Wc, const float* __restrict__ bc,
    float* __restrict__ A)
{
    int row = blockIdx.x, c = threadIdx.x;
    float a = tanhf(ga[(size_t)row * DD + c]);
    float g = 1.f / (1.f + __expf(-gb[(size_t)row * DD + c]));
    float s = blockSum256(a * g * Wc[c]);
    if (c == 0) A[row] = s + bc[0];
}

// ---- softmax stats over a vector -----------------------------------------
__global__ void __launch_bounds__(256) smstats_k(
    const float* __restrict__ A, int n, float* __restrict__ mZ)
{
    int tid = threadIdx.x;
    float mx = -1e30f;
    for (int i = tid; i < n; i += 256) mx = fmaxf(mx, A[i]);
    mx = blockMax256(mx);
    float s = 0.f;
    for (int i = tid; i < n; i += 256) s += __expf(A[i] - mx);
    s = blockSum256(s);
    if (tid == 0) { mZ[0] = mx; mZ[1] = s; }
}

// h[c] += sum_i exp(A[i]-m) * X[i][c]
__global__ void __launch_bounds__(256) wsum_k(
    const float* __restrict__ A, const float* __restrict__ X,
    const float* __restrict__ mZ, float* __restrict__ h, int n)
{
    __shared__ float w[256];
    int i0 = blockIdx.x * 256, c = threadIdx.x;
    float m = mZ[0];
    int cnt = min(256, n - i0);
    if (c < cnt) w[c] = __expf(A[i0 + c] - m);
    __syncthreads();
    float acc = 0.f;
    for (int ii = 0; ii < cnt; ii++) acc += w[ii] * X[(size_t)(i0 + ii) * DD + c];
    atomicAdd(&h[c], acc);
}

// out[d] = [relu]( bias[d] + sum_c (v[c]*invZ) * W[c][d] ), Cout = 256
__global__ void __launch_bounds__(256) matvec_k(
    const float* __restrict__ v, const float* __restrict__ W,
    const float* __restrict__ bias, const float* __restrict__ mZ,
    float* __restrict__ out, int Cin, int doRelu)
{
    __shared__ float vs[512];
    int d = threadIdx.x;
    float inv = mZ ? (1.f / mZ[1]) : 1.f;
    for (int c = d; c < Cin; c += 256) vs[c] = v[c] * inv;
    __syncthreads();
    float acc = bias[d];
    for (int c = 0; c < Cin; c++) acc += vs[c] * W[(size_t)c * DD + d];
    if (doRelu) acc = fmaxf(acc, 0.f);
    out[d] = acc;
}

// ------------------------- host orchestration ------------------------------
#define GETP(name, sym) float* name; { void* _p = nullptr; cudaGetSymbolAddress(&_p, sym); name = (float*)_p; }

extern "C" void kernel_launch(void* const* d_in, const int* in_sizes, int n_in,
                              void* d_out, int out_size)
{
    const float* x    = (const float*)d_in[0];
    const float* Wqkv = (const float*)d_in[1];
    const float* slin = (const float*)d_in[2];
    const float* dwcw = (const float*)d_in[3];
    const float* dwcb = (const float*)d_in[4];
    const float* Wa   = (const float*)d_in[5];
    const float* ba   = (const float*)d_in[6];
    const float* Wb   = (const float*)d_in[7];
    const float* bb   = (const float*)d_in[8];
    const float* Wc   = (const float*)d_in[9];
    const float* bc   = (const float*)d_in[10];
    const float* W1   = (const float*)d_in[11];
    const float* b1   = (const float*)d_in[12];
    const float* W2   = (const float*)d_in[13];
    const float* b2   = (const float*)d_in[14];
    const float* W3a  = (const float*)d_in[15];
    const float* b3a  = (const float*)d_in[16];
    const float* W3b  = (const float*)d_in[17];
    const float* b3b  = (const float*)d_in[18];
    const float* Wf   = (const float*)d_in[19];
    const float* bf   = (const float*)d_in[20];
    float* out = (float*)d_out;

    GETP(qkv, g_qkv);  GETP(L,  g_L);    GETP(rm, g_rm);   GETP(rz, g_rz);
    GETP(occ, g_occ);  GETP(osc, g_osc); GETP(ocp, g_ocp);
    GETP(ql, g_ql);    GETP(kl, g_kl);   GETP(ks, g_ks);   GETP(kv, g_kv);
    GETP(fm, g_fm);    GETP(t1, g_t1);   GETP(osp, g_osp);
    GETP(ga, g_ga);    GETP(gb, g_gb);
    GETP(Acc, g_Acc);  GETP(Acp, g_Acp); GETP(Asc, g_Asc); GETP(Asp, g_Asp);
    GETP(mZ, g_mZ);    GETP(h, g_h);     GETP(fbuf, g_f);  GETP(g1, g_g1);

    // 1. qkv = x @ W_qkv
    {
        dim3 grid(LDQ / 64, (NT + 127) / 128);
        sgemm<<<grid, 256>>>(x, Wqkv, qkv, nullptr, nullptr, NT, DD, LDQ);
    }
    // 2. small-key attention (self-celltypes, cross-path)
    attn_small_k<<<(MC + 7) / 8, 256>>>(qkv, 0,  MC, osc);
    attn_small_k<<<NP / 8,       256>>>(qkv, MC, NP, ocp);
    // 3. cross-celltypes (softmax over 65536 keys)
    cac_logits_k<<<NP / 8, 256>>>(qkv, L);
    cac_rowstats<<<MC, 256>>>(L, rm, rz);
    zerok<<<(MC * DD + 255) / 256, 256>>>(occ, MC * DD);
    cac_out_k<<<dim3(NP / 512, 2), 256>>>(L, rm, qkv + (size_t)MC * LDQ + 2 * DD, occ);
    occ_scale_k<<<MC, 256>>>(occ, rz);
    // 4. linear attention branch
    linearize_k<<<NP, 256>>>(qkv, slin, ql, 0);
    linearize_k<<<NP, 256>>>(qkv, slin, kl, DD);
    zerok<<<1, 256>>>(ks, DD);
    colsum_k<<<256, 256>>>(kl, ks);
    zfac_k<<<NP, 256>>>(ql, ks);
    zerok<<<DD * DD / 256, 256>>>(kv, DD * DD);
    atb_gemm<<<dim3(4, 4, 64), 256>>>(kl, DD, qkv + (size_t)MC * LDQ + 2 * DD, LDQ, kv, 1024);
    dwconv_k<<<NP, 256>>>(qkv, dwcw, dwcb, fm);
    {
        dim3 grid(DD / 64, (NP + 127) / 128);
        sgemm<<<grid, 256>>>(ql, kv, t1, nullptr, fm, NP, DD, DD);   // out_s + fm
        sgemm<<<grid, 256>>>(t1, Wf, osp, bf, nullptr, NP, DD, DD);  // out_self_path
    }
    // 5. gated attention scalars
    {
        const float* Xs[4] = { occ, ocp, osc, osp };
        int ns[4]          = { MC,  NP,  MC,  NP  };
        float* As[4]       = { Acc, Acp, Asc, Asp };
        for (int t = 0; t < 4; t++) {
            dim3 grid(DD / 64, (ns[t] + 127) / 128);
            sgemm<<<grid, 256>>>(Xs[t], Wa, ga, ba, nullptr, ns[t], DD, DD);
            sgemm<<<grid, 256>>>(Xs[t], Wb, gb, bb, nullptr, ns[t], DD, DD);
            gated_k<<<ns[t], 256>>>(ga, gb, Wc, bc, As[t]);
        }
    }
    // 6. fusion heads
    smstats_k<<<1, 256>>>(Acc, MC, mZ + 0);
    smstats_k<<<1, 256>>>(Acp, NP, mZ + 2);
    smstats_k<<<1, 256>>>(Asc, MC, mZ + 4);
    smstats_k<<<1, 256>>>(Asp, NP, mZ + 6);
    zerok<<<4, 256>>>(h, 4 * DD);
    wsum_k<<<1,        256>>>(Acc, occ, mZ + 0, h + 0 * DD, MC);
    wsum_k<<<NP / 256, 256>>>(Acp, ocp, mZ + 2, h + 1 * DD, NP);
    wsum_k<<<1,        256>>>(Asc, osc, mZ + 4, h + 2 * DD, MC);
    wsum_k<<<NP / 256, 256>>>(Asp, osp, mZ + 6, h + 3 * DD, NP);
    // fusion_cross -> out[0:256]
    matvec_k<<<1, 256>>>(h + 0 * DD, W1, b1, mZ + 0, fbuf + 0 * DD, DD, 1);
    matvec_k<<<1, 256>>>(h + 1 * DD, W2, b2, mZ + 2, fbuf + 1 * DD, DD, 1);
    matvec_k<<<1, 256>>>(fbuf + 0 * DD, W3a, b3a, nullptr, g1 + 0 * DD, 2 * DD, 1);
    matvec_k<<<1, 256>>>(g1 + 0 * DD, W3b, b3b, nullptr, out + 0 * DD, DD, 1);
    // fusion_self -> out[256:512]
    matvec_k<<<1, 256>>>(h + 2 * DD, W1, b1, mZ + 4, fbuf + 2 * DD, DD, 1);
    matvec_k<<<1, 256>>>(h + 3 * DD, W2, b2, mZ + 6, fbuf + 3 * DD, DD, 1);
    matvec_k<<<1, 256>>>(fbuf + 2 * DD, W3a, b3a, nullptr, g1 + 1 * DD, 2 * DD, 1);
    matvec_k<<<1, 256>>>(g1 + 1 * DD, W3b, b3b, nullptr, out + 1 * DD, DD, 1);
}